// round 8
// baseline (speedup 1.0000x reference)
#include <cuda_runtime.h>
#include <math.h>
#include <stdint.h>

#define B_  2
#define T_  4096
#define C_  1024
#define H_  16
#define HD_ 64
#define W_  256
#define NW_ (T_/W_)
#define M_  (B_*T_)

// Scratch (no cudaMalloc allowed)
__device__ float g_q[(size_t)M_*C_];
__device__ float g_k[(size_t)M_*C_];
__device__ float g_v[(size_t)M_*C_];
__device__ float g_y[(size_t)M_*C_];

// ===========================================================================
// helpers (baseline ISA only)
// ===========================================================================
__device__ __forceinline__ uint32_t f2tf32(float f) {
    uint32_t r;
    asm("cvt.rna.tf32.f32 %0, %1;" : "=r"(r) : "f"(f));
    return r;
}

__device__ __forceinline__ uint32_t smem_u32(const void* p) {
    uint32_t a;
    asm("{ .reg .u64 t; cvta.to.shared.u64 t, %1; cvt.u32.u64 %0, t; }"
        : "=r"(a) : "l"(p));
    return a;
}

__device__ __forceinline__ void cp_async16(uint32_t dst, const void* src) {
    asm volatile("cp.async.ca.shared.global [%0], [%1], 16;"
                 :: "r"(dst), "l"(src) : "memory");
}
#define CP_COMMIT() asm volatile("cp.async.commit_group;" ::: "memory")
#define CP_WAIT1()  asm volatile("cp.async.wait_group 1;" ::: "memory")

// m16n8k8 tf32 MMA, D += A*B (row.col), fp32 accumulate
__device__ __forceinline__ void mma_tf32(float* d, const uint32_t* a, const uint32_t* b) {
    asm volatile(
        "mma.sync.aligned.m16n8k8.row.col.f32.tf32.tf32.f32 "
        "{%0,%1,%2,%3}, {%4,%5,%6,%7}, {%8,%9}, {%0,%1,%2,%3};"
        : "+f"(d[0]), "+f"(d[1]), "+f"(d[2]), "+f"(d[3])
        : "r"(a[0]), "r"(a[1]), "r"(a[2]), "r"(a[3]),
          "r"(b[0]), "r"(b[1]));
}

// ===========================================================================
// tf32 GEMM (NT): C[m][n] = sum_k A[m][k] * Wt[n][k]
// CTA 128x128, BK=32, cp.async 3-stage ring (raw fp32 in smem, cvt.rna at
// fragment load -> numerics identical to R5). One __syncthreads per chunk.
// 2 CTAs/SM (regs<=128). 8 warps (2x4), warp tile 64x32.
// ROPE=1: rotary fused in epilogue.
// ===========================================================================
#define SA 36                          // smem row stride in floats (144B, 16B-aligned)
#define STAGE_F (2 * 128 * SA)         // A+B per stage = 9216 floats
#define GEMM_SMEM_BYTES (3 * STAGE_F * 4)   // 110592 B

template<int ROPE>
__global__ __launch_bounds__(256, 2)
void gemm_mma(const float* __restrict__ A, const float* __restrict__ Wt,
              float* __restrict__ Cout)
{
    extern __shared__ float sm[];
    const uint32_t smb = smem_u32(sm);

    const int tid  = threadIdx.x;
    const int wid  = tid >> 5, lane = tid & 31;
    const int wm   = wid >> 2, wn = wid & 3;     // 2 x 4 warp grid
    const int g    = lane >> 2, tig = lane & 3;  // fragment coords
    const int m0   = blockIdx.y * 128, n0 = blockIdx.x * 128;

    // staging mapping: row = tid>>1 (0..127), half = tid&1 (16 floats each)
    const int row  = tid >> 1;
    const int half = tid & 1;
    const float* Ag = A  + (size_t)(m0 + row) * C_ + half * 16;
    const float* Bg = Wt + (size_t)(n0 + row) * C_ + half * 16;
    const uint32_t dA = smb + (uint32_t)(row * SA + half * 16) * 4;
    const uint32_t dB = dA + 128 * SA * 4;

    float acc[16][4];
#pragma unroll
    for (int i = 0; i < 16; i++)
#pragma unroll
        for (int j = 0; j < 4; j++) acc[i][j] = 0.f;

    // ---- prologue: stage chunks 0,1 into ring slots 0,1 ----
#pragma unroll
    for (int j = 0; j < 4; j++) {
        cp_async16(dA + j * 16, Ag + j * 4);
        cp_async16(dB + j * 16, Bg + j * 4);
    }
    CP_COMMIT();
#pragma unroll
    for (int j = 0; j < 4; j++) {
        cp_async16(dA + STAGE_F * 4 + j * 16, Ag + 32 + j * 4);
        cp_async16(dB + STAGE_F * 4 + j * 16, Bg + 32 + j * 4);
    }
    CP_COMMIT();

    int slot = 0;                       // c % 3
    for (int c = 0; c < 32; c++) {
        CP_WAIT1();                     // chunk c landed (chunk c+1 may fly)
        __syncthreads();                // cross-thread visibility

        const float* sA = sm + slot * STAGE_F + (wm * 64) * SA;
        const float* sB = sm + slot * STAGE_F + 128 * SA + (wn * 32) * SA;

#pragma unroll
        for (int ks = 0; ks < 4; ks++) {
            const int kb = ks * 8;
            uint32_t afr[4][4], bfr[4][2];
#pragma unroll
            for (int mt = 0; mt < 4; mt++) {
                const float* p = sA + (mt * 16 + g) * SA + kb + tig;
                afr[mt][0] = f2tf32(p[0]);
                afr[mt][1] = f2tf32(p[8 * SA]);
                afr[mt][2] = f2tf32(p[4]);
                afr[mt][3] = f2tf32(p[8 * SA + 4]);
            }
#pragma unroll
            for (int nt = 0; nt < 4; nt++) {
                const float* p = sB + (nt * 8 + g) * SA + kb + tig;
                bfr[nt][0] = f2tf32(p[0]);
                bfr[nt][1] = f2tf32(p[4]);
            }
#pragma unroll
            for (int mt = 0; mt < 4; mt++)
#pragma unroll
                for (int nt = 0; nt < 4; nt++)
                    mma_tf32(acc[mt * 4 + nt], afr[mt], bfr[nt]);
        }

        // stage chunk c+2 into slot (c+2)%3  (== slot of chunk c-1; safe:
        // everyone finished chunk c-1 before the barrier above)
        if (c + 2 < 32) {
            const int s2 = (slot + 2 >= 3) ? slot - 1 : slot + 2;
            const uint32_t dA2 = dA + s2 * STAGE_F * 4;
            const uint32_t dB2 = dB + s2 * STAGE_F * 4;
            const int k0 = (c + 2) * 32;
#pragma unroll
            for (int j = 0; j < 4; j++) {
                cp_async16(dA2 + j * 16, Ag + k0 + j * 4);
                cp_async16(dB2 + j * 16, Bg + k0 + j * 4);
            }
        }
        CP_COMMIT();                    // keep group count in lockstep
        slot = (slot + 1 >= 3) ? 0 : slot + 1;
    }

    // -------- epilogue --------
    const int mbase = m0 + wm * 64;
    const int nbase = n0 + wn * 32;
#pragma unroll
    for (int nt = 0; nt < 4; nt++) {
        const int nn = nbase + nt * 8 + 2 * tig;
        float invf = 1.f, sv0, cv0, sv1, cv1;
        if (ROPE) {
            const int ip = (nn & (HD_ - 1)) >> 1;
            invf = (float)exp(-0.28782313662425572 * (double)ip); // ln(1e4)/32
        }
#pragma unroll
        for (int mt = 0; mt < 4; mt++) {
            const float* cc = acc[mt * 4 + nt];
            const int r0 = mbase + mt * 16 + g;
            const int r1 = r0 + 8;
            float2 v01 = make_float2(cc[0], cc[1]);
            float2 v23 = make_float2(cc[2], cc[3]);
            if (ROPE) {
                sincosf((float)(r0 & (T_ - 1)) * invf, &sv0, &cv0);
                sincosf((float)(r1 & (T_ - 1)) * invf, &sv1, &cv1);
                v01 = make_float2(cc[0] * cv0 - cc[1] * sv0,
                                  cc[0] * sv0 + cc[1] * cv0);
                v23 = make_float2(cc[2] * cv1 - cc[3] * sv1,
                                  cc[2] * sv1 + cc[3] * cv1);
            }
            *(float2*)(Cout + (size_t)r0 * C_ + nn) = v01;
            *(float2*)(Cout + (size_t)r1 * C_ + nn) = v23;
        }
    }
}

// ===========================================================================
// MMA flash-attention, split-tf32 compensated.  (unchanged from R7 — passed)
// ===========================================================================
#define KP 68
#define VP 72
#define PP 36
#define OFF_KHI 0
#define OFF_KLO (OFF_KHI + 2*32*KP)
#define OFF_VHI (OFF_KLO + 2*32*KP)
#define OFF_VLO (OFF_VHI + 2*32*VP)
#define OFF_P   (OFF_VLO + 2*32*VP)
#define ATTN_SMEM_BYTES ((OFF_P + 8*16*PP) * 4)   // 90112

__global__ __launch_bounds__(256)
void attn_mma(const float* __restrict__ Q, const float* __restrict__ Kg,
              const float* __restrict__ Vg, float* __restrict__ Y)
{
    extern __shared__ float smf[];

    const int w = blockIdx.x >> 1, qseg = blockIdx.x & 1;
    const int h = blockIdx.y, b = blockIdx.z;
    const int tid  = threadIdx.x;
    const int wid  = tid >> 5, lane = tid & 31;
    const int g    = lane >> 2, tig = lane & 3;
    const size_t base = ((size_t)(b * T_ + w * W_)) * C_ + h * HD_;

    const int srow = tid >> 3;           // 0..31
    const int scol = (tid & 7) * 8;      // 0,8,..,56

    uint32_t qhi[8][4], qlo[8][4];
    {
        const int qb = qseg * 128 + wid * 16;
        const float* Qp = Q + base + (size_t)qb * C_;
#pragma unroll
        for (int ks = 0; ks < 8; ks++) {
            const int cidx = ks * 8 + tig;
            float v0 = 0.125f * Qp[(size_t)g * C_ + cidx];
            float v1 = 0.125f * Qp[(size_t)(g + 8) * C_ + cidx];
            float v2 = 0.125f * Qp[(size_t)g * C_ + cidx + 4];
            float v3 = 0.125f * Qp[(size_t)(g + 8) * C_ + cidx + 4];
            qhi[ks][0] = f2tf32(v0); qlo[ks][0] = f2tf32(v0 - __uint_as_float(qhi[ks][0]));
            qhi[ks][1] = f2tf32(v1); qlo[ks][1] = f2tf32(v1 - __uint_as_float(qhi[ks][1]));
            qhi[ks][2] = f2tf32(v2); qlo[ks][2] = f2tf32(v2 - __uint_as_float(qhi[ks][2]));
            qhi[ks][3] = f2tf32(v3); qlo[ks][3] = f2tf32(v3 - __uint_as_float(qhi[ks][3]));
        }
    }

    {
        const float* kr = Kg + base + (size_t)srow * C_ + scol;
        const float* vr = Vg + base + (size_t)srow * C_ + scol;
#pragma unroll
        for (int hh = 0; hh < 2; hh++) {
            float4 kv = *(const float4*)(kr + hh * 4);
            uint4 h4, l4;
            h4.x = f2tf32(kv.x); l4.x = f2tf32(kv.x - __uint_as_float(h4.x));
            h4.y = f2tf32(kv.y); l4.y = f2tf32(kv.y - __uint_as_float(h4.y));
            h4.z = f2tf32(kv.z); l4.z = f2tf32(kv.z - __uint_as_float(h4.z));
            h4.w = f2tf32(kv.w); l4.w = f2tf32(kv.w - __uint_as_float(h4.w));
            *(uint4*)(smf + OFF_KHI + srow * KP + scol + hh * 4) = h4;
            *(uint4*)(smf + OFF_KLO + srow * KP + scol + hh * 4) = l4;
            float4 vv = *(const float4*)(vr + hh * 4);
            h4.x = f2tf32(vv.x); l4.x = f2tf32(vv.x - __uint_as_float(h4.x));
            h4.y = f2tf32(vv.y); l4.y = f2tf32(vv.y - __uint_as_float(h4.y));
            h4.z = f2tf32(vv.z); l4.z = f2tf32(vv.z - __uint_as_float(h4.z));
            h4.w = f2tf32(vv.w); l4.w = f2tf32(vv.w - __uint_as_float(h4.w));
            *(uint4*)(smf + OFF_VHI + srow * VP + scol + hh * 4) = h4;
            *(uint4*)(smf + OFF_VLO + srow * VP + scol + hh * 4) = l4;
        }
    }
    __syncthreads();

    float oacc[8][4];
#pragma unroll
    for (int nt = 0; nt < 8; nt++)
#pragma unroll
        for (int j = 0; j < 4; j++) oacc[nt][j] = 0.f;
    float mrow[2] = {-1e30f, -1e30f};
    float lrow[2] = {0.f, 0.f};

    float* Pw = smf + OFF_P + wid * 16 * PP;

    for (int c = 0; c < 8; c++) {
        const int buf = c & 1;

        if (c < 7) {
            const int kc1 = (c + 1) * 32;
            const float* kr = Kg + base + (size_t)(kc1 + srow) * C_ + scol;
            const float* vr = Vg + base + (size_t)(kc1 + srow) * C_ + scol;
            const int bofK = (buf ^ 1) * 32 * KP + srow * KP + scol;
            const int bofV = (buf ^ 1) * 32 * VP + srow * VP + scol;
#pragma unroll
            for (int hh = 0; hh < 2; hh++) {
                float4 kv = *(const float4*)(kr + hh * 4);
                uint4 h4, l4;
                h4.x = f2tf32(kv.x); l4.x = f2tf32(kv.x - __uint_as_float(h4.x));
                h4.y = f2tf32(kv.y); l4.y = f2tf32(kv.y - __uint_as_float(h4.y));
                h4.z = f2tf32(kv.z); l4.z = f2tf32(kv.z - __uint_as_float(h4.z));
                h4.w = f2tf32(kv.w); l4.w = f2tf32(kv.w - __uint_as_float(h4.w));
                *(uint4*)(smf + OFF_KHI + bofK + hh * 4) = h4;
                *(uint4*)(smf + OFF_KLO + bofK + hh * 4) = l4;
                float4 vv = *(const float4*)(vr + hh * 4);
                h4.x = f2tf32(vv.x); l4.x = f2tf32(vv.x - __uint_as_float(h4.x));
                h4.y = f2tf32(vv.y); l4.y = f2tf32(vv.y - __uint_as_float(h4.y));
                h4.z = f2tf32(vv.z); l4.z = f2tf32(vv.z - __uint_as_float(h4.z));
                h4.w = f2tf32(vv.w); l4.w = f2tf32(vv.w - __uint_as_float(h4.w));
                *(uint4*)(smf + OFF_VHI + bofV + hh * 4) = h4;
                *(uint4*)(smf + OFF_VLO + bofV + hh * 4) = l4;
            }
        }

        const uint32_t* Khi = (const uint32_t*)(smf + OFF_KHI + buf * 32 * KP);
        const uint32_t* Klo = (const uint32_t*)(smf + OFF_KLO + buf * 32 * KP);
        float sacc[4][4];
#pragma unroll
        for (int nt = 0; nt < 4; nt++)
#pragma unroll
            for (int j = 0; j < 4; j++) sacc[nt][j] = 0.f;

#pragma unroll
        for (int ks = 0; ks < 8; ks++) {
#pragma unroll
            for (int nt = 0; nt < 4; nt++) {
                const int koff = (nt * 8 + g) * KP + ks * 8 + tig;
                uint32_t bh[2], bl[2];
                bh[0] = Khi[koff];  bh[1] = Khi[koff + 4];
                bl[0] = Klo[koff];  bl[1] = Klo[koff + 4];
                mma_tf32(sacc[nt], qhi[ks], bh);
                mma_tf32(sacc[nt], qhi[ks], bl);
                mma_tf32(sacc[nt], qlo[ks], bh);
            }
        }

#pragma unroll
        for (int rr = 0; rr < 2; rr++) {
            float vmax = sacc[0][rr * 2];
#pragma unroll
            for (int nt = 0; nt < 4; nt++) {
                vmax = fmaxf(vmax, sacc[nt][rr * 2]);
                vmax = fmaxf(vmax, sacc[nt][rr * 2 + 1]);
            }
            vmax = fmaxf(vmax, __shfl_xor_sync(0xffffffffu, vmax, 1));
            vmax = fmaxf(vmax, __shfl_xor_sync(0xffffffffu, vmax, 2));
            const float mnew = fmaxf(mrow[rr], vmax);
            const float corr = __expf(mrow[rr] - mnew);
            float psum = 0.f;
            const int prow = (rr * 8 + g) * PP;
#pragma unroll
            for (int nt = 0; nt < 4; nt++) {
                uint32_t p0 = f2tf32(__expf(sacc[nt][rr * 2]     - mnew));
                uint32_t p1 = f2tf32(__expf(sacc[nt][rr * 2 + 1] - mnew));
                psum += __uint_as_float(p0) + __uint_as_float(p1);
                *(uint2*)(Pw + prow + nt * 8 + 2 * tig) = make_uint2(p0, p1);
            }
            psum += __shfl_xor_sync(0xffffffffu, psum, 1);
            psum += __shfl_xor_sync(0xffffffffu, psum, 2);
            lrow[rr] = lrow[rr] * corr + psum;
            mrow[rr] = mnew;
#pragma unroll
            for (int nt = 0; nt < 8; nt++) {
                oacc[nt][rr * 2]     *= corr;
                oacc[nt][rr * 2 + 1] *= corr;
            }
        }
        __syncwarp();

        const uint32_t* Vhi = (const uint32_t*)(smf + OFF_VHI + buf * 32 * VP);
        const uint32_t* Vlo = (const uint32_t*)(smf + OFF_VLO + buf * 32 * VP);
#pragma unroll
        for (int kt = 0; kt < 4; kt++) {
            uint32_t pa[4];
            const uint32_t* pp = (const uint32_t*)(Pw + g * PP + kt * 8 + tig);
            pa[0] = pp[0];
            pa[1] = pp[8 * PP];
            pa[2] = pp[4];
            pa[3] = pp[8 * PP + 4];
#pragma unroll
            for (int nt = 0; nt < 8; nt++) {
                const int voff = (kt * 8 + tig) * VP + nt * 8 + g;
                uint32_t bv[2];
                bv[0] = Vhi[voff];  bv[1] = Vhi[voff + 4 * VP];
                mma_tf32(oacc[nt], pa, bv);
                bv[0] = Vlo[voff];  bv[1] = Vlo[voff + 4 * VP];
                mma_tf32(oacc[nt], pa, bv);
            }
        }
        __syncthreads();
    }

    const float inv0 = 1.f / lrow[0], inv1 = 1.f / lrow[1];
    const int qb = qseg * 128 + wid * 16;
    float* Yp = Y + base + (size_t)qb * C_;
#pragma unroll
    for (int nt = 0; nt < 8; nt++) {
        const int d = nt * 8 + 2 * tig;
        *(float2*)(Yp + (size_t)g * C_ + d) =
            make_float2(oacc[nt][0] * inv0, oacc[nt][1] * inv0);
        *(float2*)(Yp + (size_t)(g + 8) * C_ + d) =
            make_float2(oacc[nt][2] * inv1, oacc[nt][3] * inv1);
    }
}

// ===========================================================================
extern "C" void kernel_launch(void* const* d_in, const int* in_sizes, int n_in,
                              void* d_out, int out_size)
{
    const float* x  = (const float*)d_in[0];
    const float* wq = (const float*)d_in[1];
    const float* wk = (const float*)d_in[2];
    const float* wv = (const float*)d_in[3];
    const float* wo = (const float*)d_in[4];
    float* out = (float*)d_out;

    float *q, *k, *v, *y;
    cudaGetSymbolAddress((void**)&q, g_q);
    cudaGetSymbolAddress((void**)&k, g_k);
    cudaGetSymbolAddress((void**)&v, g_v);
    cudaGetSymbolAddress((void**)&y, g_y);

    cudaFuncSetAttribute(gemm_mma<1>, cudaFuncAttributeMaxDynamicSharedMemorySize, GEMM_SMEM_BYTES);
    cudaFuncSetAttribute(gemm_mma<0>, cudaFuncAttributeMaxDynamicSharedMemorySize, GEMM_SMEM_BYTES);
    cudaFuncSetAttribute(attn_mma, cudaFuncAttributeMaxDynamicSharedMemorySize, ATTN_SMEM_BYTES);

    dim3 gg(C_ / 128, M_ / 128);
    gemm_mma<1><<<gg, 256, GEMM_SMEM_BYTES>>>(x, wq, q);
    gemm_mma<1><<<gg, 256, GEMM_SMEM_BYTES>>>(x, wk, k);
    gemm_mma<0><<<gg, 256, GEMM_SMEM_BYTES>>>(x, wv, v);

    dim3 ga(NW_ * 2, H_, B_);
    attn_mma<<<ga, 256, ATTN_SMEM_BYTES>>>(q, k, v, y);

    gemm_mma<0><<<gg, 256, GEMM_SMEM_BYTES>>>(y, wo, out);
}

// round 9
// speedup vs baseline: 1.1325x; 1.1325x over previous
#include <cuda_runtime.h>
#include <math.h>
#include <stdint.h>

#define B_  2
#define T_  4096
#define C_  1024
#define H_  16
#define HD_ 64
#define W_  256
#define NW_ (T_/W_)
#define M_  (B_*T_)

// Scratch (no cudaMalloc allowed)
__device__ float g_q[(size_t)M_*C_];
__device__ float g_k[(size_t)M_*C_];
__device__ float g_v[(size_t)M_*C_];
__device__ float g_y[(size_t)M_*C_];

// ===========================================================================
// helpers (baseline ISA only)
// ===========================================================================
__device__ __forceinline__ uint32_t f2tf32(float f) {
    uint32_t r;
    asm("cvt.rna.tf32.f32 %0, %1;" : "=r"(r) : "f"(f));
    return r;
}

__device__ __forceinline__ uint32_t smem_u32(const void* p) {
    uint32_t a;
    asm("{ .reg .u64 t; cvta.to.shared.u64 t, %1; cvt.u32.u64 %0, t; }"
        : "=r"(a) : "l"(p));
    return a;
}

__device__ __forceinline__ void cp_async16(uint32_t dst, const void* src) {
    asm volatile("cp.async.ca.shared.global [%0], [%1], 16;"
                 :: "r"(dst), "l"(src) : "memory");
}
#define CP_COMMIT() asm volatile("cp.async.commit_group;" ::: "memory")
#define CP_WAIT1()  asm volatile("cp.async.wait_group 1;" ::: "memory")

// m16n8k8 tf32 MMA, D += A*B (row.col), fp32 accumulate
__device__ __forceinline__ void mma_tf32(float* d, const uint32_t* a, const uint32_t* b) {
    asm volatile(
        "mma.sync.aligned.m16n8k8.row.col.f32.tf32.tf32.f32 "
        "{%0,%1,%2,%3}, {%4,%5,%6,%7}, {%8,%9}, {%0,%1,%2,%3};"
        : "+f"(d[0]), "+f"(d[1]), "+f"(d[2]), "+f"(d[3])
        : "r"(a[0]), "r"(a[1]), "r"(a[2]), "r"(a[3]),
          "r"(b[0]), "r"(b[1]));
}

// ===========================================================================
// tf32 GEMM (NT): C[m][n] = sum_k A[m][k] * Wt[n][k]
// CTA tile 128x256, 512 threads = 16 warps (2 x 8), warp tile 64x32
// (unchanged micro-kernel from R5). BK=32, cp.async 2-stage ring (raw fp32
// in smem, cvt.rna at fragment load). 16 warps on one CTA/SM = 4 warps/SMSP.
// ROPE=1: rotary fused in epilogue.
// ===========================================================================
#define SA 36                          // smem row stride in floats
#define A_F (128 * SA)                 // A floats per stage = 4608
#define BT_F (256 * SA)                // B floats per stage = 9216
#define STAGE_F (A_F + BT_F)           // 13824
#define GEMM_SMEM_BYTES (2 * STAGE_F * 4)   // 110592 B

template<int ROPE>
__global__ __launch_bounds__(512)
void gemm_mma(const float* __restrict__ A, const float* __restrict__ Wt,
              float* __restrict__ Cout)
{
    extern __shared__ float sm[];
    const uint32_t smb = smem_u32(sm);

    const int tid  = threadIdx.x;
    const int wid  = tid >> 5, lane = tid & 31;
    const int wm   = wid >> 3, wn = wid & 7;     // 2 x 8 warp grid
    const int g    = lane >> 2, tig = lane & 3;  // fragment coords
    const int m0   = blockIdx.y * 128, n0 = blockIdx.x * 256;

    // staging mapping (512 threads):
    // A tile 128x32: 1024 float4 -> 2 per thread: row=tid>>2, c4=(tid&3)*2
    // B tile 256x32: 2048 float4 -> 4 per thread: row=tid>>1, c4=(tid&1)*4
    const int arow = tid >> 2, ac4 = (tid & 3) * 2;
    const int brow = tid >> 1, bc4 = (tid & 1) * 4;
    const float* AgK = A  + (size_t)(m0 + arow) * C_ + ac4 * 4;
    const float* BgK = Wt + (size_t)(n0 + brow) * C_ + bc4 * 4;
    const uint32_t dA0 = smb + (uint32_t)(arow * SA + ac4 * 4) * 4;
    const uint32_t dB0 = smb + (uint32_t)(A_F + brow * SA + bc4 * 4) * 4;

    float acc[16][4];
#pragma unroll
    for (int i = 0; i < 16; i++)
#pragma unroll
        for (int j = 0; j < 4; j++) acc[i][j] = 0.f;

    auto stage = [&](int k0, int s) {
        const uint32_t off = (uint32_t)s * STAGE_F * 4;
        cp_async16(dA0 + off,      AgK + k0);
        cp_async16(dA0 + off + 16, AgK + k0 + 4);
        cp_async16(dB0 + off,      BgK + k0);
        cp_async16(dB0 + off + 16, BgK + k0 + 4);
        cp_async16(dB0 + off + 32, BgK + k0 + 8);
        cp_async16(dB0 + off + 48, BgK + k0 + 12);
    };

    // ---- prologue: chunks 0,1 into stages 0,1 ----
    stage(0, 0);  CP_COMMIT();
    stage(32, 1); CP_COMMIT();

    for (int c = 0; c < 32; c++) {
        CP_WAIT1();                     // chunk c landed (chunk c+1 may fly)
        __syncthreads();

        const float* sA = sm + (c & 1) * STAGE_F + (wm * 64) * SA;
        const float* sB = sm + (c & 1) * STAGE_F + A_F + (wn * 32) * SA;

#pragma unroll
        for (int ks = 0; ks < 4; ks++) {
            const int kb = ks * 8;
            uint32_t afr[4][4], bfr[4][2];
#pragma unroll
            for (int mt = 0; mt < 4; mt++) {
                const float* p = sA + (mt * 16 + g) * SA + kb + tig;
                afr[mt][0] = f2tf32(p[0]);
                afr[mt][1] = f2tf32(p[8 * SA]);
                afr[mt][2] = f2tf32(p[4]);
                afr[mt][3] = f2tf32(p[8 * SA + 4]);
            }
#pragma unroll
            for (int nt = 0; nt < 4; nt++) {
                const float* p = sB + (nt * 8 + g) * SA + kb + tig;
                bfr[nt][0] = f2tf32(p[0]);
                bfr[nt][1] = f2tf32(p[4]);
            }
#pragma unroll
            for (int mt = 0; mt < 4; mt++)
#pragma unroll
                for (int nt = 0; nt < 4; nt++)
                    mma_tf32(acc[mt * 4 + nt], afr[mt], bfr[nt]);
        }

        __syncthreads();                // everyone done reading stage c&1
        if (c + 2 < 32) stage((c + 2) * 32, c & 1);
        CP_COMMIT();                    // keep group count in lockstep
    }

    // -------- epilogue --------
    const int mbase = m0 + wm * 64;
    const int nbase = n0 + wn * 32;
#pragma unroll
    for (int nt = 0; nt < 4; nt++) {
        const int nn = nbase + nt * 8 + 2 * tig;
        float invf = 1.f, sv0, cv0, sv1, cv1;
        if (ROPE) {
            const int ip = (nn & (HD_ - 1)) >> 1;
            invf = (float)exp(-0.28782313662425572 * (double)ip); // ln(1e4)/32
        }
#pragma unroll
        for (int mt = 0; mt < 4; mt++) {
            const float* cc = acc[mt * 4 + nt];
            const int r0 = mbase + mt * 16 + g;
            const int r1 = r0 + 8;
            float2 v01 = make_float2(cc[0], cc[1]);
            float2 v23 = make_float2(cc[2], cc[3]);
            if (ROPE) {
                sincosf((float)(r0 & (T_ - 1)) * invf, &sv0, &cv0);
                sincosf((float)(r1 & (T_ - 1)) * invf, &sv1, &cv1);
                v01 = make_float2(cc[0] * cv0 - cc[1] * sv0,
                                  cc[0] * sv0 + cc[1] * cv0);
                v23 = make_float2(cc[2] * cv1 - cc[3] * sv1,
                                  cc[2] * sv1 + cc[3] * cv1);
            }
            *(float2*)(Cout + (size_t)r0 * C_ + nn) = v01;
            *(float2*)(Cout + (size_t)r1 * C_ + nn) = v23;
        }
    }
}

// ===========================================================================
// MMA flash-attention, split-tf32 compensated.  (unchanged from R7 — passed)
// ===========================================================================
#define KP 68
#define VP 72
#define PP 36
#define OFF_KHI 0
#define OFF_KLO (OFF_KHI + 2*32*KP)
#define OFF_VHI (OFF_KLO + 2*32*KP)
#define OFF_VLO (OFF_VHI + 2*32*VP)
#define OFF_P   (OFF_VLO + 2*32*VP)
#define ATTN_SMEM_BYTES ((OFF_P + 8*16*PP) * 4)   // 90112

__global__ __launch_bounds__(256)
void attn_mma(const float* __restrict__ Q, const float* __restrict__ Kg,
              const float* __restrict__ Vg, float* __restrict__ Y)
{
    extern __shared__ float smf[];

    const int w = blockIdx.x >> 1, qseg = blockIdx.x & 1;
    const int h = blockIdx.y, b = blockIdx.z;
    const int tid  = threadIdx.x;
    const int wid  = tid >> 5, lane = tid & 31;
    const int g    = lane >> 2, tig = lane & 3;
    const size_t base = ((size_t)(b * T_ + w * W_)) * C_ + h * HD_;

    const int srow = tid >> 3;           // 0..31
    const int scol = (tid & 7) * 8;      // 0,8,..,56

    uint32_t qhi[8][4], qlo[8][4];
    {
        const int qb = qseg * 128 + wid * 16;
        const float* Qp = Q + base + (size_t)qb * C_;
#pragma unroll
        for (int ks = 0; ks < 8; ks++) {
            const int cidx = ks * 8 + tig;
            float v0 = 0.125f * Qp[(size_t)g * C_ + cidx];
            float v1 = 0.125f * Qp[(size_t)(g + 8) * C_ + cidx];
            float v2 = 0.125f * Qp[(size_t)g * C_ + cidx + 4];
            float v3 = 0.125f * Qp[(size_t)(g + 8) * C_ + cidx + 4];
            qhi[ks][0] = f2tf32(v0); qlo[ks][0] = f2tf32(v0 - __uint_as_float(qhi[ks][0]));
            qhi[ks][1] = f2tf32(v1); qlo[ks][1] = f2tf32(v1 - __uint_as_float(qhi[ks][1]));
            qhi[ks][2] = f2tf32(v2); qlo[ks][2] = f2tf32(v2 - __uint_as_float(qhi[ks][2]));
            qhi[ks][3] = f2tf32(v3); qlo[ks][3] = f2tf32(v3 - __uint_as_float(qhi[ks][3]));
        }
    }

    {
        const float* kr = Kg + base + (size_t)srow * C_ + scol;
        const float* vr = Vg + base + (size_t)srow * C_ + scol;
#pragma unroll
        for (int hh = 0; hh < 2; hh++) {
            float4 kv = *(const float4*)(kr + hh * 4);
            uint4 h4, l4;
            h4.x = f2tf32(kv.x); l4.x = f2tf32(kv.x - __uint_as_float(h4.x));
            h4.y = f2tf32(kv.y); l4.y = f2tf32(kv.y - __uint_as_float(h4.y));
            h4.z = f2tf32(kv.z); l4.z = f2tf32(kv.z - __uint_as_float(h4.z));
            h4.w = f2tf32(kv.w); l4.w = f2tf32(kv.w - __uint_as_float(h4.w));
            *(uint4*)(smf + OFF_KHI + srow * KP + scol + hh * 4) = h4;
            *(uint4*)(smf + OFF_KLO + srow * KP + scol + hh * 4) = l4;
            float4 vv = *(const float4*)(vr + hh * 4);
            h4.x = f2tf32(vv.x); l4.x = f2tf32(vv.x - __uint_as_float(h4.x));
            h4.y = f2tf32(vv.y); l4.y = f2tf32(vv.y - __uint_as_float(h4.y));
            h4.z = f2tf32(vv.z); l4.z = f2tf32(vv.z - __uint_as_float(h4.z));
            h4.w = f2tf32(vv.w); l4.w = f2tf32(vv.w - __uint_as_float(h4.w));
            *(uint4*)(smf + OFF_VHI + srow * VP + scol + hh * 4) = h4;
            *(uint4*)(smf + OFF_VLO + srow * VP + scol + hh * 4) = l4;
        }
    }
    __syncthreads();

    float oacc[8][4];
#pragma unroll
    for (int nt = 0; nt < 8; nt++)
#pragma unroll
        for (int j = 0; j < 4; j++) oacc[nt][j] = 0.f;
    float mrow[2] = {-1e30f, -1e30f};
    float lrow[2] = {0.f, 0.f};

    float* Pw = smf + OFF_P + wid * 16 * PP;

    for (int c = 0; c < 8; c++) {
        const int buf = c & 1;

        if (c < 7) {
            const int kc1 = (c + 1) * 32;
            const float* kr = Kg + base + (size_t)(kc1 + srow) * C_ + scol;
            const float* vr = Vg + base + (size_t)(kc1 + srow) * C_ + scol;
            const int bofK = (buf ^ 1) * 32 * KP + srow * KP + scol;
            const int bofV = (buf ^ 1) * 32 * VP + srow * VP + scol;
#pragma unroll
            for (int hh = 0; hh < 2; hh++) {
                float4 kv = *(const float4*)(kr + hh * 4);
                uint4 h4, l4;
                h4.x = f2tf32(kv.x); l4.x = f2tf32(kv.x - __uint_as_float(h4.x));
                h4.y = f2tf32(kv.y); l4.y = f2tf32(kv.y - __uint_as_float(h4.y));
                h4.z = f2tf32(kv.z); l4.z = f2tf32(kv.z - __uint_as_float(h4.z));
                h4.w = f2tf32(kv.w); l4.w = f2tf32(kv.w - __uint_as_float(h4.w));
                *(uint4*)(smf + OFF_KHI + bofK + hh * 4) = h4;
                *(uint4*)(smf + OFF_KLO + bofK + hh * 4) = l4;
                float4 vv = *(const float4*)(vr + hh * 4);
                h4.x = f2tf32(vv.x); l4.x = f2tf32(vv.x - __uint_as_float(h4.x));
                h4.y = f2tf32(vv.y); l4.y = f2tf32(vv.y - __uint_as_float(h4.y));
                h4.z = f2tf32(vv.z); l4.z = f2tf32(vv.z - __uint_as_float(h4.z));
                h4.w = f2tf32(vv.w); l4.w = f2tf32(vv.w - __uint_as_float(h4.w));
                *(uint4*)(smf + OFF_VHI + bofV + hh * 4) = h4;
                *(uint4*)(smf + OFF_VLO + bofV + hh * 4) = l4;
            }
        }

        const uint32_t* Khi = (const uint32_t*)(smf + OFF_KHI + buf * 32 * KP);
        const uint32_t* Klo = (const uint32_t*)(smf + OFF_KLO + buf * 32 * KP);
        float sacc[4][4];
#pragma unroll
        for (int nt = 0; nt < 4; nt++)
#pragma unroll
            for (int j = 0; j < 4; j++) sacc[nt][j] = 0.f;

#pragma unroll
        for (int ks = 0; ks < 8; ks++) {
#pragma unroll
            for (int nt = 0; nt < 4; nt++) {
                const int koff = (nt * 8 + g) * KP + ks * 8 + tig;
                uint32_t bh[2], bl[2];
                bh[0] = Khi[koff];  bh[1] = Khi[koff + 4];
                bl[0] = Klo[koff];  bl[1] = Klo[koff + 4];
                mma_tf32(sacc[nt], qhi[ks], bh);
                mma_tf32(sacc[nt], qhi[ks], bl);
                mma_tf32(sacc[nt], qlo[ks], bh);
            }
        }

#pragma unroll
        for (int rr = 0; rr < 2; rr++) {
            float vmax = sacc[0][rr * 2];
#pragma unroll
            for (int nt = 0; nt < 4; nt++) {
                vmax = fmaxf(vmax, sacc[nt][rr * 2]);
                vmax = fmaxf(vmax, sacc[nt][rr * 2 + 1]);
            }
            vmax = fmaxf(vmax, __shfl_xor_sync(0xffffffffu, vmax, 1));
            vmax = fmaxf(vmax, __shfl_xor_sync(0xffffffffu, vmax, 2));
            const float mnew = fmaxf(mrow[rr], vmax);
            const float corr = __expf(mrow[rr] - mnew);
            float psum = 0.f;
            const int prow = (rr * 8 + g) * PP;
#pragma unroll
            for (int nt = 0; nt < 4; nt++) {
                uint32_t p0 = f2tf32(__expf(sacc[nt][rr * 2]     - mnew));
                uint32_t p1 = f2tf32(__expf(sacc[nt][rr * 2 + 1] - mnew));
                psum += __uint_as_float(p0) + __uint_as_float(p1);
                *(uint2*)(Pw + prow + nt * 8 + 2 * tig) = make_uint2(p0, p1);
            }
            psum += __shfl_xor_sync(0xffffffffu, psum, 1);
            psum += __shfl_xor_sync(0xffffffffu, psum, 2);
            lrow[rr] = lrow[rr] * corr + psum;
            mrow[rr] = mnew;
#pragma unroll
            for (int nt = 0; nt < 8; nt++) {
                oacc[nt][rr * 2]     *= corr;
                oacc[nt][rr * 2 + 1] *= corr;
            }
        }
        __syncwarp();

        const uint32_t* Vhi = (const uint32_t*)(smf + OFF_VHI + buf * 32 * VP);
        const uint32_t* Vlo = (const uint32_t*)(smf + OFF_VLO + buf * 32 * VP);
#pragma unroll
        for (int kt = 0; kt < 4; kt++) {
            uint32_t pa[4];
            const uint32_t* pp = (const uint32_t*)(Pw + g * PP + kt * 8 + tig);
            pa[0] = pp[0];
            pa[1] = pp[8 * PP];
            pa[2] = pp[4];
            pa[3] = pp[8 * PP + 4];
#pragma unroll
            for (int nt = 0; nt < 8; nt++) {
                const int voff = (kt * 8 + tig) * VP + nt * 8 + g;
                uint32_t bv[2];
                bv[0] = Vhi[voff];  bv[1] = Vhi[voff + 4 * VP];
                mma_tf32(oacc[nt], pa, bv);
                bv[0] = Vlo[voff];  bv[1] = Vlo[voff + 4 * VP];
                mma_tf32(oacc[nt], pa, bv);
            }
        }
        __syncthreads();
    }

    const float inv0 = 1.f / lrow[0], inv1 = 1.f / lrow[1];
    const int qb = qseg * 128 + wid * 16;
    float* Yp = Y + base + (size_t)qb * C_;
#pragma unroll
    for (int nt = 0; nt < 8; nt++) {
        const int d = nt * 8 + 2 * tig;
        *(float2*)(Yp + (size_t)g * C_ + d) =
            make_float2(oacc[nt][0] * inv0, oacc[nt][1] * inv0);
        *(float2*)(Yp + (size_t)(g + 8) * C_ + d) =
            make_float2(oacc[nt][2] * inv1, oacc[nt][3] * inv1);
    }
}

// ===========================================================================
extern "C" void kernel_launch(void* const* d_in, const int* in_sizes, int n_in,
                              void* d_out, int out_size)
{
    const float* x  = (const float*)d_in[0];
    const float* wq = (const float*)d_in[1];
    const float* wk = (const float*)d_in[2];
    const float* wv = (const float*)d_in[3];
    const float* wo = (const float*)d_in[4];
    float* out = (float*)d_out;

    float *q, *k, *v, *y;
    cudaGetSymbolAddress((void**)&q, g_q);
    cudaGetSymbolAddress((void**)&k, g_k);
    cudaGetSymbolAddress((void**)&v, g_v);
    cudaGetSymbolAddress((void**)&y, g_y);

    cudaFuncSetAttribute(gemm_mma<1>, cudaFuncAttributeMaxDynamicSharedMemorySize, GEMM_SMEM_BYTES);
    cudaFuncSetAttribute(gemm_mma<0>, cudaFuncAttributeMaxDynamicSharedMemorySize, GEMM_SMEM_BYTES);
    cudaFuncSetAttribute(attn_mma, cudaFuncAttributeMaxDynamicSharedMemorySize, ATTN_SMEM_BYTES);

    dim3 gg(C_ / 256, M_ / 128);   // (4, 64)
    gemm_mma<1><<<gg, 512, GEMM_SMEM_BYTES>>>(x, wq, q);
    gemm_mma<1><<<gg, 512, GEMM_SMEM_BYTES>>>(x, wk, k);
    gemm_mma<0><<<gg, 512, GEMM_SMEM_BYTES>>>(x, wv, v);

    dim3 ga(NW_ * 2, H_, B_);
    attn_mma<<<ga, 256, ATTN_SMEM_BYTES>>>(q, k, v, y);

    gemm_mma<0><<<gg, 512, GEMM_SMEM_BYTES>>>(y, wo, out);
}

// round 10
// speedup vs baseline: 1.2265x; 1.0831x over previous
#include <cuda_runtime.h>
#include <math.h>
#include <stdint.h>

#define B_  2
#define T_  4096
#define C_  1024
#define H_  16
#define HD_ 64
#define W_  256
#define NW_ (T_/W_)
#define M_  (B_*T_)

// Scratch (no cudaMalloc allowed)
__device__ float g_q[(size_t)M_*C_];
__device__ float g_k[(size_t)M_*C_];
__device__ float g_v[(size_t)M_*C_];
__device__ float g_y[(size_t)M_*C_];

// ===========================================================================
// helpers (baseline ISA only)
// ===========================================================================
__device__ __forceinline__ uint32_t f2tf32(float f) {
    uint32_t r;
    asm("cvt.rna.tf32.f32 %0, %1;" : "=r"(r) : "f"(f));
    return r;
}

__device__ __forceinline__ uint32_t smem_u32(const void* p) {
    uint32_t a;
    asm("{ .reg .u64 t; cvta.to.shared.u64 t, %1; cvt.u32.u64 %0, t; }"
        : "=r"(a) : "l"(p));
    return a;
}

__device__ __forceinline__ void cp_async16(uint32_t dst, const void* src) {
    asm volatile("cp.async.ca.shared.global [%0], [%1], 16;"
                 :: "r"(dst), "l"(src) : "memory");
}
#define CP_COMMIT() asm volatile("cp.async.commit_group;" ::: "memory")
#define CP_WAIT1()  asm volatile("cp.async.wait_group 1;" ::: "memory")

// m16n8k8 tf32 MMA, D += A*B (row.col), fp32 accumulate
__device__ __forceinline__ void mma_tf32(float* d, const uint32_t* a, const uint32_t* b) {
    asm volatile(
        "mma.sync.aligned.m16n8k8.row.col.f32.tf32.tf32.f32 "
        "{%0,%1,%2,%3}, {%4,%5,%6,%7}, {%8,%9}, {%0,%1,%2,%3};"
        : "+f"(d[0]), "+f"(d[1]), "+f"(d[2]), "+f"(d[3])
        : "r"(a[0]), "r"(a[1]), "r"(a[2]), "r"(a[3]),
          "r"(b[0]), "r"(b[1]));
}

// ===========================================================================
// tf32 GEMM (NT): C[m][n] = sum_k A[m][k] * Wt[n][k]
// CTA tile 128x256, 512 threads = 16 warps (2 x 8), warp tile 64x32.
// BK=32, cp.async 3-STAGE ring, ONE __syncthreads per chunk (staging for
// chunk c+2 goes into the slot vacated by chunk c-1; the barrier at the top
// of iteration c guarantees all warps finished reading chunk c-1).
// cvt.rna at fragment load. ROPE=1: rotary fused in epilogue.
// ===========================================================================
#define SA 36                          // smem row stride in floats
#define A_F (128 * SA)                 // 4608 floats
#define BT_F (256 * SA)                // 9216 floats
#define STAGE_F (A_F + BT_F)           // 13824
#define GEMM_SMEM_BYTES (3 * STAGE_F * 4)   // 165888 B

template<int ROPE>
__global__ __launch_bounds__(512)
void gemm_mma(const float* __restrict__ A, const float* __restrict__ Wt,
              float* __restrict__ Cout)
{
    extern __shared__ float sm[];
    const uint32_t smb = smem_u32(sm);

    const int tid  = threadIdx.x;
    const int wid  = tid >> 5, lane = tid & 31;
    const int wm   = wid >> 3, wn = wid & 7;     // 2 x 8 warp grid
    const int g    = lane >> 2, tig = lane & 3;  // fragment coords
    const int m0   = blockIdx.y * 128, n0 = blockIdx.x * 256;

    const int arow = tid >> 2, ac4 = (tid & 3) * 2;
    const int brow = tid >> 1, bc4 = (tid & 1) * 4;
    const float* AgK = A  + (size_t)(m0 + arow) * C_ + ac4 * 4;
    const float* BgK = Wt + (size_t)(n0 + brow) * C_ + bc4 * 4;
    const uint32_t dA0 = smb + (uint32_t)(arow * SA + ac4 * 4) * 4;
    const uint32_t dB0 = smb + (uint32_t)(A_F + brow * SA + bc4 * 4) * 4;

    float acc[16][4];
#pragma unroll
    for (int i = 0; i < 16; i++)
#pragma unroll
        for (int j = 0; j < 4; j++) acc[i][j] = 0.f;

    auto stage = [&](int k0, int s) {
        const uint32_t off = (uint32_t)s * (STAGE_F * 4);
        cp_async16(dA0 + off,      AgK + k0);
        cp_async16(dA0 + off + 16, AgK + k0 + 4);
        cp_async16(dB0 + off,      BgK + k0);
        cp_async16(dB0 + off + 16, BgK + k0 + 4);
        cp_async16(dB0 + off + 32, BgK + k0 + 8);
        cp_async16(dB0 + off + 48, BgK + k0 + 12);
    };

    // ---- prologue: chunks 0,1 -> slots 0,1 ----
    stage(0, 0);  CP_COMMIT();
    stage(32, 1); CP_COMMIT();

    int slot = 0;
    for (int c = 0; c < 32; c++) {
        CP_WAIT1();                     // chunk c landed (c+1 may fly)
        __syncthreads();                // also: all warps done reading c-1

        // stage chunk c+2 into slot(c+2)%3 == slot(c-1) — safe per barrier
        if (c + 2 < 32) {
            int s2 = slot + 2; if (s2 >= 3) s2 -= 3;
            stage((c + 2) * 32, s2);
        }
        CP_COMMIT();                    // keep group count in lockstep

        const float* sA = sm + slot * STAGE_F + (wm * 64) * SA;
        const float* sB = sm + slot * STAGE_F + A_F + (wn * 32) * SA;

#pragma unroll
        for (int ks = 0; ks < 4; ks++) {
            const int kb = ks * 8;
            uint32_t afr[4][4], bfr[4][2];
#pragma unroll
            for (int mt = 0; mt < 4; mt++) {
                const float* p = sA + (mt * 16 + g) * SA + kb + tig;
                afr[mt][0] = f2tf32(p[0]);
                afr[mt][1] = f2tf32(p[8 * SA]);
                afr[mt][2] = f2tf32(p[4]);
                afr[mt][3] = f2tf32(p[8 * SA + 4]);
            }
#pragma unroll
            for (int nt = 0; nt < 4; nt++) {
                const float* p = sB + (nt * 8 + g) * SA + kb + tig;
                bfr[nt][0] = f2tf32(p[0]);
                bfr[nt][1] = f2tf32(p[4]);
            }
#pragma unroll
            for (int mt = 0; mt < 4; mt++)
#pragma unroll
                for (int nt = 0; nt < 4; nt++)
                    mma_tf32(acc[mt * 4 + nt], afr[mt], bfr[nt]);
        }

        slot++; if (slot >= 3) slot = 0;
    }

    // -------- epilogue --------
    const int mbase = m0 + wm * 64;
    const int nbase = n0 + wn * 32;
#pragma unroll
    for (int nt = 0; nt < 4; nt++) {
        const int nn = nbase + nt * 8 + 2 * tig;
        float invf = 1.f, sv0, cv0, sv1, cv1;
        if (ROPE) {
            const int ip = (nn & (HD_ - 1)) >> 1;
            invf = (float)exp(-0.28782313662425572 * (double)ip); // ln(1e4)/32
        }
#pragma unroll
        for (int mt = 0; mt < 4; mt++) {
            const float* cc = acc[mt * 4 + nt];
            const int r0 = mbase + mt * 16 + g;
            const int r1 = r0 + 8;
            float2 v01 = make_float2(cc[0], cc[1]);
            float2 v23 = make_float2(cc[2], cc[3]);
            if (ROPE) {
                sincosf((float)(r0 & (T_ - 1)) * invf, &sv0, &cv0);
                sincosf((float)(r1 & (T_ - 1)) * invf, &sv1, &cv1);
                v01 = make_float2(cc[0] * cv0 - cc[1] * sv0,
                                  cc[0] * sv0 + cc[1] * cv0);
                v23 = make_float2(cc[2] * cv1 - cc[3] * sv1,
                                  cc[2] * sv1 + cc[3] * cv1);
            }
            *(float2*)(Cout + (size_t)r0 * C_ + nn) = v01;
            *(float2*)(Cout + (size_t)r1 * C_ + nn) = v23;
        }
    }
}

// ===========================================================================
// MMA flash-attention, plain tf32 (R7 structure, lo-terms removed).
// Grid (2*nW, H, B), 256 thr = 8 warps, warp owns 16 queries.
// K/V streamed in 32-key chunks, double-buffered. S = Q@K^T (32 MMAs),
// online softmax (P tf32-rounded; l summed from rounded P), O += P@V (32).
// 54KB smem + <=128 regs -> 2 CTAs/SM.
// ===========================================================================
#define KP 68
#define VP 72
#define PP 36
#define OFF_K 0
#define OFF_V (OFF_K + 2*32*KP)
#define OFF_P (OFF_V + 2*32*VP)
#define ATTN_SMEM_BYTES ((OFF_P + 8*16*PP) * 4)   // 54272

__global__ __launch_bounds__(256, 2)
void attn_mma(const float* __restrict__ Q, const float* __restrict__ Kg,
              const float* __restrict__ Vg, float* __restrict__ Y)
{
    extern __shared__ float smf[];

    const int w = blockIdx.x >> 1, qseg = blockIdx.x & 1;
    const int h = blockIdx.y, b = blockIdx.z;
    const int tid  = threadIdx.x;
    const int wid  = tid >> 5, lane = tid & 31;
    const int g    = lane >> 2, tig = lane & 3;
    const size_t base = ((size_t)(b * T_ + w * W_)) * C_ + h * HD_;

    const int srow = tid >> 3;           // 0..31
    const int scol = (tid & 7) * 8;      // 0,8,..,56

    // ---- Q fragments (16 rows per warp), pre-scaled tf32 ----
    uint32_t qf[8][4];
    {
        const int qb = qseg * 128 + wid * 16;
        const float* Qp = Q + base + (size_t)qb * C_;
#pragma unroll
        for (int ks = 0; ks < 8; ks++) {
            const int cidx = ks * 8 + tig;
            qf[ks][0] = f2tf32(0.125f * Qp[(size_t)g * C_ + cidx]);
            qf[ks][1] = f2tf32(0.125f * Qp[(size_t)(g + 8) * C_ + cidx]);
            qf[ks][2] = f2tf32(0.125f * Qp[(size_t)g * C_ + cidx + 4]);
            qf[ks][3] = f2tf32(0.125f * Qp[(size_t)(g + 8) * C_ + cidx + 4]);
        }
    }

    // ---- stage chunk 0 into buf 0 ----
    {
        const float* kr = Kg + base + (size_t)srow * C_ + scol;
        const float* vr = Vg + base + (size_t)srow * C_ + scol;
#pragma unroll
        for (int hh = 0; hh < 2; hh++) {
            float4 kv = *(const float4*)(kr + hh * 4);
            *(uint4*)(smf + OFF_K + srow * KP + scol + hh * 4) =
                make_uint4(f2tf32(kv.x), f2tf32(kv.y), f2tf32(kv.z), f2tf32(kv.w));
            float4 vv = *(const float4*)(vr + hh * 4);
            *(uint4*)(smf + OFF_V + srow * VP + scol + hh * 4) =
                make_uint4(f2tf32(vv.x), f2tf32(vv.y), f2tf32(vv.z), f2tf32(vv.w));
        }
    }
    __syncthreads();

    float oacc[8][4];
#pragma unroll
    for (int nt = 0; nt < 8; nt++)
#pragma unroll
        for (int j = 0; j < 4; j++) oacc[nt][j] = 0.f;
    float mrow[2] = {-1e30f, -1e30f};
    float lrow[2] = {0.f, 0.f};

    float* Pw = smf + OFF_P + wid * 16 * PP;

    for (int c = 0; c < 8; c++) {
        const int buf = c & 1;

        // ---- stage next chunk into buf^1 ----
        if (c < 7) {
            const int kc1 = (c + 1) * 32;
            const float* kr = Kg + base + (size_t)(kc1 + srow) * C_ + scol;
            const float* vr = Vg + base + (size_t)(kc1 + srow) * C_ + scol;
            const int bofK = OFF_K + (buf ^ 1) * 32 * KP + srow * KP + scol;
            const int bofV = OFF_V + (buf ^ 1) * 32 * VP + srow * VP + scol;
#pragma unroll
            for (int hh = 0; hh < 2; hh++) {
                float4 kv = *(const float4*)(kr + hh * 4);
                *(uint4*)(smf + bofK + hh * 4) =
                    make_uint4(f2tf32(kv.x), f2tf32(kv.y), f2tf32(kv.z), f2tf32(kv.w));
                float4 vv = *(const float4*)(vr + hh * 4);
                *(uint4*)(smf + bofV + hh * 4) =
                    make_uint4(f2tf32(vv.x), f2tf32(vv.y), f2tf32(vv.z), f2tf32(vv.w));
            }
        }

        // ---- S = Q @ K^T ----
        const uint32_t* Ku = (const uint32_t*)(smf + OFF_K + buf * 32 * KP);
        float sacc[4][4];
#pragma unroll
        for (int nt = 0; nt < 4; nt++)
#pragma unroll
            for (int j = 0; j < 4; j++) sacc[nt][j] = 0.f;

#pragma unroll
        for (int ks = 0; ks < 8; ks++) {
#pragma unroll
            for (int nt = 0; nt < 4; nt++) {
                const int koff = (nt * 8 + g) * KP + ks * 8 + tig;
                uint32_t bk[2];
                bk[0] = Ku[koff];
                bk[1] = Ku[koff + 4];
                mma_tf32(sacc[nt], qf[ks], bk);
            }
        }

        // ---- online softmax; stage tf32-rounded P; l from rounded P ----
#pragma unroll
        for (int rr = 0; rr < 2; rr++) {
            float vmax = sacc[0][rr * 2];
#pragma unroll
            for (int nt = 0; nt < 4; nt++) {
                vmax = fmaxf(vmax, sacc[nt][rr * 2]);
                vmax = fmaxf(vmax, sacc[nt][rr * 2 + 1]);
            }
            vmax = fmaxf(vmax, __shfl_xor_sync(0xffffffffu, vmax, 1));
            vmax = fmaxf(vmax, __shfl_xor_sync(0xffffffffu, vmax, 2));
            const float mnew = fmaxf(mrow[rr], vmax);
            const float corr = __expf(mrow[rr] - mnew);
            float psum = 0.f;
            const int prow = (rr * 8 + g) * PP;
#pragma unroll
            for (int nt = 0; nt < 4; nt++) {
                uint32_t p0 = f2tf32(__expf(sacc[nt][rr * 2]     - mnew));
                uint32_t p1 = f2tf32(__expf(sacc[nt][rr * 2 + 1] - mnew));
                psum += __uint_as_float(p0) + __uint_as_float(p1);
                *(uint2*)(Pw + prow + nt * 8 + 2 * tig) = make_uint2(p0, p1);
            }
            psum += __shfl_xor_sync(0xffffffffu, psum, 1);
            psum += __shfl_xor_sync(0xffffffffu, psum, 2);
            lrow[rr] = lrow[rr] * corr + psum;
            mrow[rr] = mnew;
#pragma unroll
            for (int nt = 0; nt < 8; nt++) {
                oacc[nt][rr * 2]     *= corr;
                oacc[nt][rr * 2 + 1] *= corr;
            }
        }
        __syncwarp();

        // ---- O += P @ V ----
        const uint32_t* Vu = (const uint32_t*)(smf + OFF_V + buf * 32 * VP);
#pragma unroll
        for (int kt = 0; kt < 4; kt++) {
            uint32_t pa[4];
            const uint32_t* pp = (const uint32_t*)(Pw + g * PP + kt * 8 + tig);
            pa[0] = pp[0];
            pa[1] = pp[8 * PP];
            pa[2] = pp[4];
            pa[3] = pp[8 * PP + 4];
#pragma unroll
            for (int nt = 0; nt < 8; nt++) {
                const int voff = (kt * 8 + tig) * VP + nt * 8 + g;
                uint32_t bv[2];
                bv[0] = Vu[voff];
                bv[1] = Vu[voff + 4 * VP];
                mma_tf32(oacc[nt], pa, bv);
            }
        }
        __syncthreads();   // all reads of buf done; staged buf^1 visible
    }

    // ---- epilogue: normalize & store ----
    const float inv0 = 1.f / lrow[0], inv1 = 1.f / lrow[1];
    const int qb = qseg * 128 + wid * 16;
    float* Yp = Y + base + (size_t)qb * C_;
#pragma unroll
    for (int nt = 0; nt < 8; nt++) {
        const int d = nt * 8 + 2 * tig;
        *(float2*)(Yp + (size_t)g * C_ + d) =
            make_float2(oacc[nt][0] * inv0, oacc[nt][1] * inv0);
        *(float2*)(Yp + (size_t)(g + 8) * C_ + d) =
            make_float2(oacc[nt][2] * inv1, oacc[nt][3] * inv1);
    }
}

// ===========================================================================
extern "C" void kernel_launch(void* const* d_in, const int* in_sizes, int n_in,
                              void* d_out, int out_size)
{
    const float* x  = (const float*)d_in[0];
    const float* wq = (const float*)d_in[1];
    const float* wk = (const float*)d_in[2];
    const float* wv = (const float*)d_in[3];
    const float* wo = (const float*)d_in[4];
    float* out = (float*)d_out;

    float *q, *k, *v, *y;
    cudaGetSymbolAddress((void**)&q, g_q);
    cudaGetSymbolAddress((void**)&k, g_k);
    cudaGetSymbolAddress((void**)&v, g_v);
    cudaGetSymbolAddress((void**)&y, g_y);

    cudaFuncSetAttribute(gemm_mma<1>, cudaFuncAttributeMaxDynamicSharedMemorySize, GEMM_SMEM_BYTES);
    cudaFuncSetAttribute(gemm_mma<0>, cudaFuncAttributeMaxDynamicSharedMemorySize, GEMM_SMEM_BYTES);
    cudaFuncSetAttribute(attn_mma, cudaFuncAttributeMaxDynamicSharedMemorySize, ATTN_SMEM_BYTES);

    dim3 gg(C_ / 256, M_ / 128);   // (4, 64)
    gemm_mma<1><<<gg, 512, GEMM_SMEM_BYTES>>>(x, wq, q);
    gemm_mma<1><<<gg, 512, GEMM_SMEM_BYTES>>>(x, wk, k);
    gemm_mma<0><<<gg, 512, GEMM_SMEM_BYTES>>>(x, wv, v);

    dim3 ga(NW_ * 2, H_, B_);
    attn_mma<<<ga, 256, ATTN_SMEM_BYTES>>>(q, k, v, y);

    gemm_mma<0><<<gg, 512, GEMM_SMEM_BYTES>>>(y, wo, out);
}